// round 4
// baseline (speedup 1.0000x reference)
#include <cuda_runtime.h>
#include <stdint.h>

#define NMAXC  100000
#define NBW    3200          // bitset words for 100k nodes
#define F_IN   128
#define HDIM   16
#define EMB    100
#define AA     5
#define HID    128
#define L2CAP  400000
#define L3CAP  100000
#define GN     64
#define XPITCH 132
#define TPB    256

// -------- scratch (device globals; zero-initialized at load, re-zeroed at end of each run) ----
__device__ unsigned g_arrive;
__device__ __align__(256) float g_deg [NMAXC];          // deg-sum, then dinv in-place
__device__ __align__(256) float g_h1p [NMAXC * HDIM];
__device__ __align__(256) float g_agg1[NMAXC * HDIM];
__device__ __align__(256) float g_h2p [NMAXC * HDIM];
__device__ __align__(256) float g_agg2[NMAXC * HDIM];
__device__ __align__(256) float g_h2  [NMAXC * HDIM];
__device__ __align__(256) float g_agg3[AA * HDIM];
__device__ __align__(256) unsigned g_n1bits[NBW];
__device__ __align__(256) unsigned g_n2bits[NBW];
__device__ __align__(256) int g_list2[L2CAP];
__device__ __align__(256) int g_list3[L3CAP];
__device__ __align__(256) int g_nl1[NMAXC];
__device__ __align__(256) int g_nl2[NMAXC];
__device__ __align__(256) int g_cnt[4];   // [0]=list2 [1]=list3 [2]=nl1 [3]=nl2

struct ShGemm { float xs[GN * XPITCH]; float ws[F_IN * HDIM]; };
struct ShHead { float v[AA * HDIM]; float z[AA * EMB]; float o1[HID]; float o2[HID]; };
struct ShN1   { float w2[HDIM * HDIM]; float b1v[HDIM]; };
union ShU { ShGemm g; ShHead h; ShN1 n1; };

__device__ __forceinline__ void mark2_push(int node) {
    unsigned bit = 1u << (node & 31);
    unsigned old = atomicOr(&g_n2bits[node >> 5], bit);
    if (!(old & bit)) {
        int k = atomicAdd(&g_cnt[3], 1);
        if (k < NMAXC) g_nl2[k] = node;
        float4 z = make_float4(0.f, 0.f, 0.f, 0.f);
        float4* p = (float4*)(g_agg2 + node * HDIM);
        p[0] = z; p[1] = z; p[2] = z; p[3] = z;
    }
}

__device__ __forceinline__ void mark1_push(int node) {
    unsigned bit = 1u << (node & 31);
    unsigned old = atomicOr(&g_n1bits[node >> 5], bit);
    if (!(old & bit)) {
        int k = atomicAdd(&g_cnt[2], 1);
        if (k < NMAXC) g_nl1[k] = node;
        float4 z = make_float4(0.f, 0.f, 0.f, 0.f);
        float4* p = (float4*)(g_agg1 + node * HDIM);
        p[0] = z; p[1] = z; p[2] = z; p[3] = z;
    }
}

// software grid barrier: idx = 1,2,3,... (g_arrive memset to 0 before launch)
__device__ __forceinline__ void gsync(int nblk, int idx) {
    __syncthreads();
    if (threadIdx.x == 0) {
        __threadfence();
        unsigned target = (unsigned)nblk * (unsigned)idx;
        atomicAdd(&g_arrive, 1u);
        while (*(volatile unsigned*)&g_arrive < target) __nanosleep(32);
    }
    __syncthreads();
}

__global__ void __launch_bounds__(TPB, 4) k_mega(
    const float* __restrict__ x, const float* __restrict__ W1,
    const int* __restrict__ src, const int* __restrict__ dst,
    const float* __restrict__ ew, const int* __restrict__ pos,
    const float* __restrict__ b1, const float* __restrict__ W2,
    const float* __restrict__ b2,
    const float* __restrict__ W3, const float* __restrict__ b3,
    const float* __restrict__ fcW1, const float* __restrict__ fcb1,
    const float* __restrict__ fcW2, const float* __restrict__ fcb2,
    const float* __restrict__ fcW3, const float* __restrict__ fcb3,
    float* __restrict__ out, int n, int E, int gB)
{
    __shared__ ShU sh;
    const int t    = threadIdx.x;
    const int b    = blockIdx.x;
    const int nblk = gridDim.x;
    const int gtid = b * TPB + t;
    const int gstr = nblk * TPB;
    const bool vec = ((E & 3) == 0);
    const int  EV  = vec ? (E >> 2) : 0;

    const int p0 = __ldg(pos + 0), p1 = __ldg(pos + 1), p2 = __ldg(pos + 2),
              p3 = __ldg(pos + 3), p4 = __ldg(pos + 4);

    // ================= P0: gemm (blocks < gB)  |  scan1 (deg + need2 + list3) =================
    if (b < gB) {
        int numTiles = (n + GN - 1) / GN;
        for (int tb = b; tb < numTiles; tb += gB) {
            __syncthreads();
#pragma unroll
            for (int k = 0; k < 8; k++) sh.g.ws[t + k * 256] = __ldg(W1 + t + k * 256);
            int n0 = tb * GN;
#pragma unroll
            for (int k = 0; k < 8; k++) {
                int f = t + k * 256, r = f >> 5, c = f & 31;
                float4 v = make_float4(0.f, 0.f, 0.f, 0.f);
                if (n0 + r < n) v = *(const float4*)(x + (size_t)(n0 + r) * F_IN + c * 4);
                *(float4*)(sh.g.xs + r * XPITCH + c * 4) = v;
            }
            __syncthreads();
            int r = t >> 2, og = (t & 3) * 4;
            const float* xr = sh.g.xs + r * XPITCH;
            float4 acc = make_float4(0.f, 0.f, 0.f, 0.f);
#pragma unroll 8
            for (int j = 0; j < F_IN; j += 4) {
                float4 xv = *(const float4*)(xr + j);
                const float* wb = sh.g.ws + j * HDIM + og;
                float4 w0 = *(const float4*)(wb);
                float4 w1v = *(const float4*)(wb + HDIM);
                float4 w2v = *(const float4*)(wb + 2 * HDIM);
                float4 w3v = *(const float4*)(wb + 3 * HDIM);
                acc.x = fmaf(xv.x, w0.x, acc.x);  acc.y = fmaf(xv.x, w0.y, acc.y);
                acc.z = fmaf(xv.x, w0.z, acc.z);  acc.w = fmaf(xv.x, w0.w, acc.w);
                acc.x = fmaf(xv.y, w1v.x, acc.x); acc.y = fmaf(xv.y, w1v.y, acc.y);
                acc.z = fmaf(xv.y, w1v.z, acc.z); acc.w = fmaf(xv.y, w1v.w, acc.w);
                acc.x = fmaf(xv.z, w2v.x, acc.x); acc.y = fmaf(xv.z, w2v.y, acc.y);
                acc.z = fmaf(xv.z, w2v.z, acc.z); acc.w = fmaf(xv.z, w2v.w, acc.w);
                acc.x = fmaf(xv.w, w3v.x, acc.x); acc.y = fmaf(xv.w, w3v.y, acc.y);
                acc.z = fmaf(xv.w, w3v.z, acc.z); acc.w = fmaf(xv.w, w3v.w, acc.w);
            }
            if (n0 + r < n) *(float4*)(g_h1p + (n0 + r) * HDIM + og) = acc;
        }
    } else {
        int sb = b - gB, sn = nblk - gB;
        if (sb == 0 && t < AA) { int p = __ldg(pos + t); if (p >= 0) mark2_push(p); }
        for (int vb = sb * TPB; vb < EV; vb += sn * TPB) {
            int v = vb + t;
            if (v < EV) {
                int4 d4 = __ldg((const int4*)dst + v);
                float4 w4 = __ldg((const float4*)ew + v);
                atomicAdd(&g_deg[d4.x], w4.x);
                atomicAdd(&g_deg[d4.y], w4.y);
                atomicAdd(&g_deg[d4.z], w4.z);
                atomicAdd(&g_deg[d4.w], w4.w);
                int dd[4] = {d4.x, d4.y, d4.z, d4.w};
#pragma unroll
                for (int j = 0; j < 4; j++) {
                    int d = dd[j];
                    if (d == p0 || d == p1 || d == p2 || d == p3 || d == p4) {
                        int e = v * 4 + j;
                        mark2_push(__ldg(src + e));
                        int k = atomicAdd(&g_cnt[1], 1);
                        if (k < L3CAP) g_list3[k] = e;
                    }
                }
            }
        }
        for (int e = EV * 4 + sb * TPB + t; e < E; e += sn * TPB) {
            int d = __ldg(dst + e);
            atomicAdd(&g_deg[d], __ldg(ew + e));
            if (d == p0 || d == p1 || d == p2 || d == p3 || d == p4) {
                mark2_push(__ldg(src + e));
                int k = atomicAdd(&g_cnt[1], 1);
                if (k < L3CAP) g_list3[k] = e;
            }
        }
    }
    gsync(nblk, 1);

    // ================= P1: dinv = rsqrt(1+deg)  +  nl2->nl1  +  scan2 (need1 + list2) ========
    if ((n & 3) == 0) {
        int nv4 = n >> 2;
        for (int v = gtid; v < nv4; v += gstr) {
            float4 dv = *(float4*)(g_deg + v * 4);
            dv.x = rsqrtf(1.f + dv.x); dv.y = rsqrtf(1.f + dv.y);
            dv.z = rsqrtf(1.f + dv.z); dv.w = rsqrtf(1.f + dv.w);
            *(float4*)(g_deg + v * 4) = dv;
        }
    } else {
        for (int i = gtid; i < n; i += gstr) g_deg[i] = rsqrtf(1.f + g_deg[i]);
    }
    {
        int c3 = __ldcg(&g_cnt[3]); if (c3 > NMAXC) c3 = NMAXC;
        for (int i = gtid; i < c3; i += gstr) mark1_push(g_nl2[i]);
        for (int vb = b * TPB; vb < EV; vb += gstr) {
            int v = vb + t;
            if (v < EV) {
                int4 d4 = __ldg((const int4*)dst + v);
                int dd[4] = {d4.x, d4.y, d4.z, d4.w};
#pragma unroll
                for (int j = 0; j < 4; j++) {
                    int d = dd[j];
                    if ((g_n2bits[d >> 5] >> (d & 31)) & 1u) {
                        int e = v * 4 + j;
                        mark1_push(__ldg(src + e));
                        int k = atomicAdd(&g_cnt[0], 1);
                        if (k < L2CAP) g_list2[k] = e;
                    }
                }
            }
        }
        for (int e = EV * 4 + gtid; e < E; e += gstr) {
            int d = __ldg(dst + e);
            if ((g_n2bits[d >> 5] >> (d & 31)) & 1u) {
                mark1_push(__ldg(src + e));
                int k = atomicAdd(&g_cnt[0], 1);
                if (k < L2CAP) g_list2[k] = e;
            }
        }
    }
    gsync(nblk, 2);

    // ================= P2: edge1 — full scan, warp-cooperative gated scatter ==================
    {
        int lane = t & 31;
        for (int vb = b * TPB; vb < EV; vb += gstr) {
            int v = vb + t;
            bool inr = v < EV;
            int4 d4 = make_int4(0, 0, 0, 0);
            if (inr) d4 = __ldg((const int4*)dst + v);
            int dd[4] = {d4.x, d4.y, d4.z, d4.w};
#pragma unroll
            for (int j = 0; j < 4; j++) {
                int d = dd[j];
                bool hit = inr && ((__ldcg(&g_n1bits[d >> 5]) >> (d & 31)) & 1u);
                unsigned m = __ballot_sync(0xffffffffu, hit);
                while (m) {
                    int l = __ffs(m) - 1;
                    m &= m - 1;
                    int vv = __shfl_sync(0xffffffffu, v, l);
                    int ds = __shfl_sync(0xffffffffu, d, l);
                    int e = vv * 4 + j;
                    int ss = __ldg(src + e);
                    float nrm = g_deg[ss] * __ldg(ew + e) * g_deg[ds];
                    if (lane < HDIM)
                        atomicAdd(&g_agg1[ds * HDIM + lane], nrm * g_h1p[ss * HDIM + lane]);
                }
            }
        }
        for (int e = EV * 4 + gtid; e < E; e += gstr) {
            int d = __ldg(dst + e);
            if ((__ldcg(&g_n1bits[d >> 5]) >> (d & 31)) & 1u) {
                int s = __ldg(src + e);
                float nrm = g_deg[s] * __ldg(ew + e) * g_deg[d];
#pragma unroll
                for (int k = 0; k < HDIM; k++)
                    atomicAdd(&g_agg1[d * HDIM + k], nrm * g_h1p[s * HDIM + k]);
            }
        }
    }
    gsync(nblk, 3);

    // ================= P3: node1 (compact): h1 = relu(...); h2p = h1 @ W2 =====================
    {
        sh.n1.w2[t] = __ldg(W2 + t);
        if (t < HDIM) sh.n1.b1v[t] = __ldg(b1 + t);
        __syncthreads();
        int c1 = __ldcg(&g_cnt[2]); if (c1 > NMAXC) c1 = NMAXC;
        for (int i = gtid; i < c1; i += gstr) {
            int nd = g_nl1[i];
            float di = g_deg[nd], d2 = di * di;
            float h[HDIM];
            const float4* ar = (const float4*)(g_agg1 + nd * HDIM);
            const float4* hr = (const float4*)(g_h1p + nd * HDIM);
#pragma unroll
            for (int v4 = 0; v4 < 4; v4++) {
                float4 a = ar[v4], p = hr[v4];
                h[v4*4+0] = fmaxf(a.x + d2 * p.x + sh.n1.b1v[v4*4+0], 0.f);
                h[v4*4+1] = fmaxf(a.y + d2 * p.y + sh.n1.b1v[v4*4+1], 0.f);
                h[v4*4+2] = fmaxf(a.z + d2 * p.z + sh.n1.b1v[v4*4+2], 0.f);
                h[v4*4+3] = fmaxf(a.w + d2 * p.w + sh.n1.b1v[v4*4+3], 0.f);
            }
            float* op = g_h2p + nd * HDIM;
#pragma unroll
            for (int og = 0; og < HDIM; og += 4) {
                float4 acc = make_float4(0.f, 0.f, 0.f, 0.f);
#pragma unroll
                for (int k = 0; k < HDIM; k++) {
                    const float* wr = sh.n1.w2 + k * HDIM + og;
                    acc.x = fmaf(h[k], wr[0], acc.x);
                    acc.y = fmaf(h[k], wr[1], acc.y);
                    acc.z = fmaf(h[k], wr[2], acc.z);
                    acc.w = fmaf(h[k], wr[3], acc.w);
                }
                *(float4*)(op + og) = acc;
            }
        }
    }
    gsync(nblk, 4);

    // ================= P4: edge2 over compact list2, thread per (edge,k) ======================
    {
        int c2 = __ldcg(&g_cnt[0]); if (c2 > L2CAP) c2 = L2CAP;
        int total = c2 * HDIM;
        for (int i = gtid; i < total; i += gstr) {
            int e = g_list2[i >> 4], k = i & 15;
            int s = __ldg(src + e), d = __ldg(dst + e);
            float nrm = g_deg[s] * __ldg(ew + e) * g_deg[d];
            atomicAdd(&g_agg2[d * HDIM + k], nrm * g_h2p[s * HDIM + k]);
        }
    }
    gsync(nblk, 5);

    // ================= P5: node2 (compact): h2 = relu(...) ====================================
    {
        int c3 = __ldcg(&g_cnt[3]); if (c3 > NMAXC) c3 = NMAXC;
        for (int i = gtid; i < c3; i += gstr) {
            int nd = g_nl2[i];
            float di = g_deg[nd], d2 = di * di;
            const float4* ar = (const float4*)(g_agg2 + nd * HDIM);
            const float4* pr = (const float4*)(g_h2p + nd * HDIM);
            float4* op = (float4*)(g_h2 + nd * HDIM);
#pragma unroll
            for (int v4 = 0; v4 < 4; v4++) {
                float4 a = ar[v4], p = pr[v4];
                float4 o;
                o.x = fmaxf(a.x + d2 * p.x + __ldg(b2 + v4*4+0), 0.f);
                o.y = fmaxf(a.y + d2 * p.y + __ldg(b2 + v4*4+1), 0.f);
                o.z = fmaxf(a.z + d2 * p.z + __ldg(b2 + v4*4+2), 0.f);
                o.w = fmaxf(a.w + d2 * p.w + __ldg(b2 + v4*4+3), 0.f);
                op[v4] = o;
            }
        }
    }
    gsync(nblk, 6);

    // ================= P6: edge3 over compact list3 into agg3 =================================
    {
        int parr[AA] = {p0, p1, p2, p3, p4};
        int c3e = __ldcg(&g_cnt[1]); if (c3e > L3CAP) c3e = L3CAP;
        int total = c3e * HDIM;
        for (int i = gtid; i < total; i += gstr) {
            int e = g_list3[i >> 4], k = i & 15;
            int s = __ldg(src + e), d = __ldg(dst + e);
            float nrm = g_deg[s] * __ldg(ew + e) * g_deg[d];
            float val = nrm * g_h2[s * HDIM + k];
#pragma unroll
            for (int a = 0; a < AA; a++)
                if (d == parr[a]) atomicAdd(&g_agg3[a * HDIM + k], val);
        }
    }
    gsync(nblk, 7);

    // ================= P7: head (block 0)  |  cleanup-for-next-replay (others) ================
    if (b == 0) {
        if (t < AA * HDIM) {
            int a = t >> 4, k = t & 15;
            int p = __ldg(pos + a);
            float val = 0.f;
            if (p >= 0) {
                float di = g_deg[p];
                val = g_agg3[t] + di * di * g_h2[p * HDIM + k];
            }
            sh.h.v[t] = val;
        }
        __syncthreads();
        for (int j = t; j < AA * EMB; j += TPB) {
            int a = j / EMB, c = j % EMB;
            int p = __ldg(pos + a);
            float acc;
            if (p < 0) acc = -1.f;
            else {
                acc = __ldg(b3 + c);
#pragma unroll
                for (int k = 0; k < HDIM; k++)
                    acc = fmaf(sh.h.v[a * HDIM + k], __ldg(W3 + k * EMB + c), acc);
            }
            sh.h.z[j] = acc;
        }
        __syncthreads();
        if (t < HID) {
            float acc = __ldg(fcb1 + t);
#pragma unroll 4
            for (int j = 0; j < AA * EMB; j++)
                acc = fmaf(sh.h.z[j], __ldg(fcW1 + j * HID + t), acc);
            sh.h.o1[t] = fmaxf(acc, 0.f);
        }
        __syncthreads();
        if (t < HID) {
            float acc = __ldg(fcb2 + t);
#pragma unroll 4
            for (int j = 0; j < HID; j++)
                acc = fmaf(sh.h.o1[j], __ldg(fcW2 + j * HID + t), acc);
            sh.h.o2[t] = fmaxf(acc, 0.f);
        }
        __syncthreads();
        if (t < AA) {
            float acc = __ldg(fcb3 + t);
#pragma unroll 4
            for (int j = 0; j < HID; j++)
                acc = fmaf(sh.h.o2[j], __ldg(fcW3 + j * AA + t), acc);
            out[t] = acc;
        }
        __syncthreads();
        if (t < AA) { int p = __ldg(pos + t); if (p >= 0) g_deg[p] = 0.f; }
        if (t < AA * HDIM) g_agg3[t] = 0.f;
    } else {
        int ct = (b - 1) * TPB + t, cs = (nblk - 1) * TPB;
        for (int i = ct; i < NBW; i += cs) { g_n1bits[i] = 0u; g_n2bits[i] = 0u; }
        if (b == 1 && t < 4) g_cnt[t] = 0;
        for (int i = ct; i < n; i += cs)
            if (i != p0 && i != p1 && i != p2 && i != p3 && i != p4) g_deg[i] = 0.f;
    }
}

extern "C" void kernel_launch(void* const* d_in, const int* in_sizes, int n_in,
                              void* d_out, int out_size) {
    const float* x    = (const float*)d_in[0];
    const int*   ei   = (const int*)  d_in[1];
    const float* ew   = (const float*)d_in[2];
    const int*   pos  = (const int*)  d_in[3];
    const float* W1   = (const float*)d_in[4];
    const float* b1   = (const float*)d_in[5];
    const float* W2   = (const float*)d_in[6];
    const float* b2   = (const float*)d_in[7];
    const float* W3   = (const float*)d_in[8];
    const float* b3   = (const float*)d_in[9];
    const float* fcW1 = (const float*)d_in[10];
    const float* fcb1 = (const float*)d_in[11];
    const float* fcW2 = (const float*)d_in[12];
    const float* fcb2 = (const float*)d_in[13];
    const float* fcW3 = (const float*)d_in[14];
    const float* fcb3 = (const float*)d_in[15];

    int N = in_sizes[0] / F_IN;
    int E = in_sizes[1] / 2;
    const int* src = ei;
    const int* dst = ei + E;
    float* out = (float*)d_out;

    void* a_arr;
    cudaGetSymbolAddress(&a_arr, g_arrive);
    cudaMemsetAsync(a_arr, 0, sizeof(unsigned));

    int dev = 0;
    cudaGetDevice(&dev);
    int sms = 148;
    cudaDeviceGetAttribute(&sms, cudaDevAttrMultiProcessorCount, dev);
    int bpm = 0;
    cudaOccupancyMaxActiveBlocksPerMultiprocessor(&bpm, k_mega, TPB, 0);
    if (bpm < 1) bpm = 1;
    int nblk = sms * bpm;
    int gB = (nblk * 2) / 5;
    if (gB < 1) gB = 1;
    if (gB >= nblk) gB = nblk - 1;

    k_mega<<<nblk, TPB>>>(x, W1, src, dst, ew, pos, b1, W2, b2, W3, b3,
                          fcW1, fcb1, fcW2, fcb2, fcW3, fcb3, out, N, E, gB);
}

// round 5
// speedup vs baseline: 1.2655x; 1.2655x over previous
#include <cuda_runtime.h>
#include <stdint.h>

#define NMAXC  100000
#define NBW    3200
#define F_IN   128
#define HDIM   16
#define EMB    100
#define AA     5
#define HID    128
#define L2CAP  400000
#define L3CAP  100000
#define GN     32
#define XPITCH 132
#define TPB    256

// ---- everything that must be zero at the start of each replay, in ONE blob ----
struct ZeroBlob {
    float    deg[NMAXC];          // weight-sum; later dinv in-place
    unsigned n1bits[NBW];
    unsigned n2bits[NBW];
    int      cnt[4];              // [0]=list2 [1]=list3 [2]=nl1 [3]=nl2
    float    agg3[AA * HDIM];
    unsigned arrive;
};
__device__ __align__(256) ZeroBlob g_z;

__device__ __align__(256) float g_h1p [NMAXC * HDIM];
__device__ __align__(256) float g_agg1[NMAXC * HDIM];
__device__ __align__(256) float g_h2p [NMAXC * HDIM];
__device__ __align__(256) float g_agg2[NMAXC * HDIM];
__device__ __align__(256) float g_h2  [NMAXC * HDIM];
__device__ __align__(256) int g_list2[L2CAP];
__device__ __align__(256) int g_list3[L3CAP];
__device__ __align__(256) int g_nl1[NMAXC];
__device__ __align__(256) int g_nl2[NMAXC];

__device__ __forceinline__ void mark2_push(int node) {
    unsigned bit = 1u << (node & 31);
    unsigned old = atomicOr(&g_z.n2bits[node >> 5], bit);
    if (!(old & bit)) {
        int k = atomicAdd(&g_z.cnt[3], 1);
        if (k < NMAXC) g_nl2[k] = node;
        float4 zz = make_float4(0.f, 0.f, 0.f, 0.f);
        float4* p = (float4*)(g_agg2 + node * HDIM);
        p[0] = zz; p[1] = zz; p[2] = zz; p[3] = zz;
    }
}

__device__ __forceinline__ void mark1_push(int node) {
    unsigned bit = 1u << (node & 31);
    unsigned old = atomicOr(&g_z.n1bits[node >> 5], bit);
    if (!(old & bit)) {
        int k = atomicAdd(&g_z.cnt[2], 1);
        if (k < NMAXC) g_nl1[k] = node;
        float4 zz = make_float4(0.f, 0.f, 0.f, 0.f);
        float4* p = (float4*)(g_agg1 + node * HDIM);
        p[0] = zz; p[1] = zz; p[2] = zz; p[3] = zz;
    }
}

// ======================= K1: gemm ∥ scanA (interleaved even/odd blocks) =======================
__global__ void __launch_bounds__(TPB) k1_gemm_scanA(
        const float* __restrict__ x, const float* __restrict__ W1,
        const int* __restrict__ src, const int* __restrict__ dst,
        const float* __restrict__ ew, const int* __restrict__ pos,
        int n, int E, int T, int S) {
    __shared__ float xs[GN * XPITCH];
    __shared__ float ws[F_IN * HDIM];
    int b = blockIdx.x, t = threadIdx.x;
    int m  = (T < S) ? T : S;
    int m2 = 2 * m;
    bool isGemm; int idx;
    if (b < m2) { isGemm = !(b & 1); idx = b >> 1; }
    else        { isGemm = (T > S); idx = m + (b - m2); }

    if (isGemm) {
        int n0 = idx * GN;
#pragma unroll
        for (int k = 0; k < 8; k++) ws[t + k * 256] = __ldg(W1 + t + k * 256);
#pragma unroll
        for (int k = 0; k < 4; k++) {
            int f = t + k * 256, r = f >> 5, c = f & 31;   // 32 rows x 32 float4
            float4 v = make_float4(0.f, 0.f, 0.f, 0.f);
            if (n0 + r < n) v = *(const float4*)(x + (size_t)(n0 + r) * F_IN + c * 4);
            *(float4*)(xs + r * XPITCH + c * 4) = v;
        }
        __syncthreads();
        int r = t >> 3, og = (t & 7) * 2;                  // 32 rows x 8 out-pairs
        const float* xr = xs + r * XPITCH;
        float2 acc = make_float2(0.f, 0.f);
#pragma unroll 8
        for (int j = 0; j < F_IN; j += 4) {
            float4 xv = *(const float4*)(xr + j);
            const float* wb = ws + j * HDIM + og;
            float2 w0 = *(const float2*)(wb);
            float2 w1 = *(const float2*)(wb + HDIM);
            float2 w2 = *(const float2*)(wb + 2 * HDIM);
            float2 w3 = *(const float2*)(wb + 3 * HDIM);
            acc.x = fmaf(xv.x, w0.x, acc.x); acc.y = fmaf(xv.x, w0.y, acc.y);
            acc.x = fmaf(xv.y, w1.x, acc.x); acc.y = fmaf(xv.y, w1.y, acc.y);
            acc.x = fmaf(xv.z, w2.x, acc.x); acc.y = fmaf(xv.z, w2.y, acc.y);
            acc.x = fmaf(xv.w, w3.x, acc.x); acc.y = fmaf(xv.w, w3.y, acc.y);
        }
        if (n0 + r < n) *(float2*)(g_h1p + (n0 + r) * HDIM + og) = acc;
    } else {
        const int p0 = __ldg(pos + 0), p1 = __ldg(pos + 1), p2 = __ldg(pos + 2),
                  p3 = __ldg(pos + 3), p4 = __ldg(pos + 4);
        if (idx == 0 && t < AA) { int p = __ldg(pos + t); if (p >= 0) mark2_push(p); }
        if ((E & 3) == 0) {
            int v = idx * 256 + t;
            if (v < (E >> 2)) {
                int4 d4 = __ldg((const int4*)dst + v);
                float4 w4 = __ldg((const float4*)ew + v);
                atomicAdd(&g_z.deg[d4.x], w4.x);
                atomicAdd(&g_z.deg[d4.y], w4.y);
                atomicAdd(&g_z.deg[d4.z], w4.z);
                atomicAdd(&g_z.deg[d4.w], w4.w);
                int dd[4] = {d4.x, d4.y, d4.z, d4.w};
#pragma unroll
                for (int j = 0; j < 4; j++) {
                    int d = dd[j];
                    if (d == p0 || d == p1 || d == p2 || d == p3 || d == p4) {
                        int e = v * 4 + j;
                        mark2_push(__ldg(src + e));
                        int k = atomicAdd(&g_z.cnt[1], 1);
                        if (k < L3CAP) g_list3[k] = e;
                    }
                }
            }
        } else {
#pragma unroll
            for (int j = 0; j < 4; j++) {
                int e = idx * 1024 + j * 256 + t;
                if (e < E) {
                    int d = __ldg(dst + e);
                    atomicAdd(&g_z.deg[d], __ldg(ew + e));
                    if (d == p0 || d == p1 || d == p2 || d == p3 || d == p4) {
                        mark2_push(__ldg(src + e));
                        int k = atomicAdd(&g_z.cnt[1], 1);
                        if (k < L3CAP) g_list3[k] = e;
                    }
                }
            }
        }
    }
}

// ======================= K2: rsqrt-prep (+nl2->nl1) ∥ scan2 =======================
__global__ void __launch_bounds__(TPB) k2_prep_scan2(
        const int* __restrict__ src, const int* __restrict__ dst,
        int n, int E, int P) {
    int b = blockIdx.x, t = threadIdx.x;
    if (b < P) {
        if ((n & 3) == 0) {
            int v = b * 256 + t;
            if (v < (n >> 2)) {
                float4 dv = *(float4*)(g_z.deg + v * 4);
                dv.x = rsqrtf(1.f + dv.x); dv.y = rsqrtf(1.f + dv.y);
                dv.z = rsqrtf(1.f + dv.z); dv.w = rsqrtf(1.f + dv.w);
                *(float4*)(g_z.deg + v * 4) = dv;
            }
        } else {
#pragma unroll
            for (int j = 0; j < 4; j++) {
                int i = b * 1024 + j * 256 + t;
                if (i < n) g_z.deg[i] = rsqrtf(1.f + g_z.deg[i]);
            }
        }
        if (b == 0) {
            int c3 = g_z.cnt[3]; if (c3 > NMAXC) c3 = NMAXC;
            for (int i = t; i < c3; i += 256) mark1_push(g_nl2[i]);
        }
    } else {
        int idx = b - P;
        if ((E & 3) == 0) {
            int v = idx * 256 + t;
            if (v < (E >> 2)) {
                int4 d4 = __ldg((const int4*)dst + v);
                int dd[4] = {d4.x, d4.y, d4.z, d4.w};
#pragma unroll
                for (int j = 0; j < 4; j++) {
                    int d = dd[j];
                    if ((g_z.n2bits[d >> 5] >> (d & 31)) & 1u) {
                        int e = v * 4 + j;
                        mark1_push(__ldg(src + e));
                        int k = atomicAdd(&g_z.cnt[0], 1);
                        if (k < L2CAP) g_list2[k] = e;
                    }
                }
            }
        } else {
#pragma unroll
            for (int j = 0; j < 4; j++) {
                int e = idx * 1024 + j * 256 + t;
                if (e < E) {
                    int d = __ldg(dst + e);
                    if ((g_z.n2bits[d >> 5] >> (d & 31)) & 1u) {
                        mark1_push(__ldg(src + e));
                        int k = atomicAdd(&g_z.cnt[0], 1);
                        if (k < L2CAP) g_list2[k] = e;
                    }
                }
            }
        }
    }
}

// ======================= K3: edge1 full scan, warp-cooperative gated scatter =======================
__global__ void __launch_bounds__(TPB) k3_edge1(
        const int* __restrict__ src, const int* __restrict__ dst,
        const float* __restrict__ ew, int E) {
    int b = blockIdx.x, t = threadIdx.x, lane = t & 31;
    if ((E & 3) == 0) {
        int v = b * 256 + t;
        bool inr = v < (E >> 2);
        int4 d4 = make_int4(0, 0, 0, 0);
        if (inr) d4 = __ldg((const int4*)dst + v);
        int dd[4] = {d4.x, d4.y, d4.z, d4.w};
#pragma unroll
        for (int j = 0; j < 4; j++) {
            int d = dd[j];
            bool hit = inr && ((g_z.n1bits[d >> 5] >> (d & 31)) & 1u);
            unsigned m = __ballot_sync(0xffffffffu, hit);
            while (m) {
                int l = __ffs(m) - 1;
                m &= m - 1;
                int vv = __shfl_sync(0xffffffffu, v, l);
                int ds = __shfl_sync(0xffffffffu, d, l);
                int e = vv * 4 + j;
                int ss = __ldg(src + e);
                float nrm = g_z.deg[ss] * __ldg(ew + e) * g_z.deg[ds];
                if (lane < HDIM)
                    atomicAdd(&g_agg1[ds * HDIM + lane], nrm * g_h1p[ss * HDIM + lane]);
            }
        }
    } else {
#pragma unroll
        for (int j = 0; j < 4; j++) {
            int e = b * 1024 + j * 256 + t;
            if (e < E) {
                int d = __ldg(dst + e);
                if ((g_z.n1bits[d >> 5] >> (d & 31)) & 1u) {
                    int s = __ldg(src + e);
                    float nrm = g_z.deg[s] * __ldg(ew + e) * g_z.deg[d];
#pragma unroll
                    for (int k = 0; k < HDIM; k++)
                        atomicAdd(&g_agg1[d * HDIM + k], nrm * g_h1p[s * HDIM + k]);
                }
            }
        }
    }
}

// ======================= K4: persistent tail: node1 -> edge2 -> node2 -> edge3 -> head =======================
__device__ __forceinline__ void gsync(int nblk, int idx) {
    __syncthreads();
    if (threadIdx.x == 0) {
        __threadfence();
        unsigned target = (unsigned)nblk * (unsigned)idx;
        atomicAdd(&g_z.arrive, 1u);
        while (*(volatile unsigned*)&g_z.arrive < target) __nanosleep(32);
        __threadfence();
    }
    __syncthreads();
}

__global__ void __launch_bounds__(TPB) k4_tail(
    const int* __restrict__ src, const int* __restrict__ dst,
    const float* __restrict__ ew, const int* __restrict__ pos,
    const float* __restrict__ b1, const float* __restrict__ W2,
    const float* __restrict__ b2,
    const float* __restrict__ W3, const float* __restrict__ b3,
    const float* __restrict__ fcW1, const float* __restrict__ fcb1,
    const float* __restrict__ fcW2, const float* __restrict__ fcb2,
    const float* __restrict__ fcW3, const float* __restrict__ fcb3,
    float* __restrict__ out)
{
    __shared__ float shw[HDIM * HDIM];
    __shared__ float shb[HDIM];
    __shared__ float shz[AA * EMB];
    __shared__ float sho1[HID];
    __shared__ float sho2[HID];
    int t = threadIdx.x, b = blockIdx.x, nblk = gridDim.x;
    int gtid = b * TPB + t, gstr = nblk * TPB;

    // --- node1 ---
    shw[t] = __ldg(W2 + t);
    if (t < HDIM) shb[t] = __ldg(b1 + t);
    __syncthreads();
    {
        int c1 = g_z.cnt[2]; if (c1 > NMAXC) c1 = NMAXC;
        for (int i = gtid; i < c1; i += gstr) {
            int nd = g_nl1[i];
            float di = g_z.deg[nd], d2 = di * di;
            float h[HDIM];
            const float4* ar = (const float4*)(g_agg1 + nd * HDIM);
            const float4* hr = (const float4*)(g_h1p + nd * HDIM);
#pragma unroll
            for (int v4 = 0; v4 < 4; v4++) {
                float4 a = ar[v4], p = hr[v4];
                h[v4*4+0] = fmaxf(a.x + d2 * p.x + shb[v4*4+0], 0.f);
                h[v4*4+1] = fmaxf(a.y + d2 * p.y + shb[v4*4+1], 0.f);
                h[v4*4+2] = fmaxf(a.z + d2 * p.z + shb[v4*4+2], 0.f);
                h[v4*4+3] = fmaxf(a.w + d2 * p.w + shb[v4*4+3], 0.f);
            }
            float* op = g_h2p + nd * HDIM;
#pragma unroll
            for (int og = 0; og < HDIM; og += 4) {
                float4 acc = make_float4(0.f, 0.f, 0.f, 0.f);
#pragma unroll
                for (int k = 0; k < HDIM; k++) {
                    const float* wr = shw + k * HDIM + og;
                    acc.x = fmaf(h[k], wr[0], acc.x);
                    acc.y = fmaf(h[k], wr[1], acc.y);
                    acc.z = fmaf(h[k], wr[2], acc.z);
                    acc.w = fmaf(h[k], wr[3], acc.w);
                }
                *(float4*)(op + og) = acc;
            }
        }
    }
    gsync(nblk, 1);

    // --- edge2 ---
    {
        int c2 = g_z.cnt[0]; if (c2 > L2CAP) c2 = L2CAP;
        int total = c2 * HDIM;
        for (int i = gtid; i < total; i += gstr) {
            int e = g_list2[i >> 4], k = i & 15;
            int s = __ldg(src + e), d = __ldg(dst + e);
            float nrm = g_z.deg[s] * __ldg(ew + e) * g_z.deg[d];
            atomicAdd(&g_agg2[d * HDIM + k], nrm * g_h2p[s * HDIM + k]);
        }
    }
    gsync(nblk, 2);

    // --- node2 ---
    {
        int c3 = g_z.cnt[3]; if (c3 > NMAXC) c3 = NMAXC;
        for (int i = gtid; i < c3; i += gstr) {
            int nd = g_nl2[i];
            float di = g_z.deg[nd], d2 = di * di;
            const float4* ar = (const float4*)(g_agg2 + nd * HDIM);
            const float4* pr = (const float4*)(g_h2p + nd * HDIM);
            float4* op = (float4*)(g_h2 + nd * HDIM);
#pragma unroll
            for (int v4 = 0; v4 < 4; v4++) {
                float4 a = ar[v4], p = pr[v4];
                float4 o;
                o.x = fmaxf(a.x + d2 * p.x + __ldg(b2 + v4*4+0), 0.f);
                o.y = fmaxf(a.y + d2 * p.y + __ldg(b2 + v4*4+1), 0.f);
                o.z = fmaxf(a.z + d2 * p.z + __ldg(b2 + v4*4+2), 0.f);
                o.w = fmaxf(a.w + d2 * p.w + __ldg(b2 + v4*4+3), 0.f);
                op[v4] = o;
            }
        }
    }
    gsync(nblk, 3);

    // --- edge3 ---
    {
        const int p0 = __ldg(pos+0), p1 = __ldg(pos+1), p2 = __ldg(pos+2),
                  p3 = __ldg(pos+3), p4 = __ldg(pos+4);
        int parr[AA] = {p0, p1, p2, p3, p4};
        int c3e = g_z.cnt[1]; if (c3e > L3CAP) c3e = L3CAP;
        int total = c3e * HDIM;
        for (int i = gtid; i < total; i += gstr) {
            int e = g_list3[i >> 4], k = i & 15;
            int s = __ldg(src + e), d = __ldg(dst + e);
            float nrm = g_z.deg[s] * __ldg(ew + e) * g_z.deg[d];
            float val = nrm * g_h2[s * HDIM + k];
#pragma unroll
            for (int a = 0; a < AA; a++)
                if (d == parr[a]) atomicAdd(&g_z.agg3[a * HDIM + k], val);
        }
    }
    gsync(nblk, 4);

    // --- head (block 0 only) ---
    if (b == 0) {
        __shared__ float shv[AA * HDIM];
        if (t < AA * HDIM) {
            int a = t >> 4, k = t & 15;
            int p = __ldg(pos + a);
            float val = 0.f;
            if (p >= 0) {
                float di = g_z.deg[p];
                val = g_z.agg3[t] + di * di * g_h2[p * HDIM + k];
            }
            shv[t] = val;
        }
        __syncthreads();
        for (int j = t; j < AA * EMB; j += TPB) {
            int a = j / EMB, c = j % EMB;
            int p = __ldg(pos + a);
            float acc;
            if (p < 0) acc = -1.f;
            else {
                acc = __ldg(b3 + c);
#pragma unroll
                for (int k = 0; k < HDIM; k++)
                    acc = fmaf(shv[a * HDIM + k], __ldg(W3 + k * EMB + c), acc);
            }
            shz[j] = acc;
        }
        __syncthreads();
        if (t < HID) {
            float acc = __ldg(fcb1 + t);
#pragma unroll 4
            for (int j = 0; j < AA * EMB; j++)
                acc = fmaf(shz[j], __ldg(fcW1 + j * HID + t), acc);
            sho1[t] = fmaxf(acc, 0.f);
        }
        __syncthreads();
        if (t < HID) {
            float acc = __ldg(fcb2 + t);
#pragma unroll 4
            for (int j = 0; j < HID; j++)
                acc = fmaf(sho1[j], __ldg(fcW2 + j * HID + t), acc);
            sho2[t] = fmaxf(acc, 0.f);
        }
        __syncthreads();
        if (t < AA) {
            float acc = __ldg(fcb3 + t);
#pragma unroll 4
            for (int j = 0; j < HID; j++)
                acc = fmaf(sho2[j], __ldg(fcW3 + j * AA + t), acc);
            out[t] = acc;
        }
    }
}

extern "C" void kernel_launch(void* const* d_in, const int* in_sizes, int n_in,
                              void* d_out, int out_size) {
    const float* x    = (const float*)d_in[0];
    const int*   ei   = (const int*)  d_in[1];
    const float* ew   = (const float*)d_in[2];
    const int*   pos  = (const int*)  d_in[3];
    const float* W1   = (const float*)d_in[4];
    const float* b1   = (const float*)d_in[5];
    const float* W2   = (const float*)d_in[6];
    const float* b2   = (const float*)d_in[7];
    const float* W3   = (const float*)d_in[8];
    const float* b3   = (const float*)d_in[9];
    const float* fcW1 = (const float*)d_in[10];
    const float* fcb1 = (const float*)d_in[11];
    const float* fcW2 = (const float*)d_in[12];
    const float* fcb2 = (const float*)d_in[13];
    const float* fcW3 = (const float*)d_in[14];
    const float* fcb3 = (const float*)d_in[15];

    int N = in_sizes[0] / F_IN;
    int E = in_sizes[1] / 2;
    const int* src = ei;
    const int* dst = ei + E;
    float* out = (float*)d_out;

    void* zp;
    cudaGetSymbolAddress(&zp, g_z);
    cudaMemsetAsync(zp, 0, sizeof(ZeroBlob));

    int T = (N + GN - 1) / GN;           // gemm tiles
    int S = (E + 1023) / 1024;           // edge chunks (1024 edges/block)
    int P = (N + 1023) / 1024;           // prep chunks

    k1_gemm_scanA<<<T + S, TPB>>>(x, W1, src, dst, ew, pos, N, E, T, S);
    k2_prep_scan2<<<P + S, TPB>>>(src, dst, N, E, P);
    k3_edge1     <<<S, TPB>>>(src, dst, ew, E);
    k4_tail      <<<64, TPB>>>(src, dst, ew, pos, b1, W2, b2, W3, b3,
                               fcW1, fcb1, fcW2, fcb2, fcW3, fcb3, out);
}

// round 6
// speedup vs baseline: 2.0748x; 1.6395x over previous
#include <cuda_runtime.h>
#include <stdint.h>

#define NMAXC  100000
#define NBW    3200
#define F_IN   128
#define HDIM   16
#define EMB    100
#define AA     5
#define HID    128
#define L2CAP  400000
#define L3CAP  100000
#define GN     32
#define XPITCH 132
#define TPB    256

// ---- everything that must be zero at the start of each replay, in ONE blob ----
struct ZeroBlob {
    float    deg[NMAXC];          // weight-sum; later dinv in-place
    unsigned n1bits[NBW];
    unsigned n2bits[NBW];
    int      cnt[4];              // [0]=list2 [1]=list3 [2]=nl1 [3]=nl2
    float    agg3[AA * HDIM];
    unsigned arrive;
};
__device__ __align__(256) ZeroBlob g_z;

__device__ __align__(256) float g_h1p [NMAXC * HDIM];
__device__ __align__(256) float g_agg1[NMAXC * HDIM];
__device__ __align__(256) float g_h2p [NMAXC * HDIM];
__device__ __align__(256) float g_agg2[NMAXC * HDIM];
__device__ __align__(256) float g_h2  [NMAXC * HDIM];
__device__ __align__(256) int g_list2[L2CAP];
__device__ __align__(256) int g_list3[L3CAP];
__device__ __align__(256) int g_nl1[NMAXC];
__device__ __align__(256) int g_nl2[NMAXC];
__device__ float g_dummy;

__device__ __forceinline__ void mark2_push(int node) {
    unsigned bit = 1u << (node & 31);
    unsigned old = atomicOr(&g_z.n2bits[node >> 5], bit);
    if (!(old & bit)) {
        int k = atomicAdd(&g_z.cnt[3], 1);
        if (k < NMAXC) g_nl2[k] = node;
        float4 zz = make_float4(0.f, 0.f, 0.f, 0.f);
        float4* p = (float4*)(g_agg2 + node * HDIM);
        p[0] = zz; p[1] = zz; p[2] = zz; p[3] = zz;
    }
}

__device__ __forceinline__ void mark1_push(int node) {
    unsigned bit = 1u << (node & 31);
    unsigned old = atomicOr(&g_z.n1bits[node >> 5], bit);
    if (!(old & bit)) {
        int k = atomicAdd(&g_z.cnt[2], 1);
        if (k < NMAXC) g_nl1[k] = node;
        float4 zz = make_float4(0.f, 0.f, 0.f, 0.f);
        float4* p = (float4*)(g_agg1 + node * HDIM);
        p[0] = zz; p[1] = zz; p[2] = zz; p[3] = zz;
    }
}

// ======================= K1: gemm ∥ scanA (interleaved even/odd blocks) =======================
__global__ void __launch_bounds__(TPB) k1_gemm_scanA(
        const float* __restrict__ x, const float* __restrict__ W1,
        const int* __restrict__ src, const int* __restrict__ dst,
        const float* __restrict__ ew, const int* __restrict__ pos,
        int n, int E, int T, int S) {
    __shared__ float xs[GN * XPITCH];
    __shared__ float ws[F_IN * HDIM];
    int b = blockIdx.x, t = threadIdx.x;
    int m  = (T < S) ? T : S;
    int m2 = 2 * m;
    bool isGemm; int idx;
    if (b < m2) { isGemm = !(b & 1); idx = b >> 1; }
    else        { isGemm = (T > S); idx = m + (b - m2); }

    if (isGemm) {
        int n0 = idx * GN;
#pragma unroll
        for (int k = 0; k < 8; k++) ws[t + k * 256] = __ldg(W1 + t + k * 256);
#pragma unroll
        for (int k = 0; k < 4; k++) {
            int f = t + k * 256, r = f >> 5, c = f & 31;
            float4 v = make_float4(0.f, 0.f, 0.f, 0.f);
            if (n0 + r < n) v = *(const float4*)(x + (size_t)(n0 + r) * F_IN + c * 4);
            *(float4*)(xs + r * XPITCH + c * 4) = v;
        }
        __syncthreads();
        int r = t >> 3, og = (t & 7) * 2;
        const float* xr = xs + r * XPITCH;
        float2 acc = make_float2(0.f, 0.f);
#pragma unroll 8
        for (int j = 0; j < F_IN; j += 4) {
            float4 xv = *(const float4*)(xr + j);
            const float* wb = ws + j * HDIM + og;
            float2 w0 = *(const float2*)(wb);
            float2 w1 = *(const float2*)(wb + HDIM);
            float2 w2 = *(const float2*)(wb + 2 * HDIM);
            float2 w3 = *(const float2*)(wb + 3 * HDIM);
            acc.x = fmaf(xv.x, w0.x, acc.x); acc.y = fmaf(xv.x, w0.y, acc.y);
            acc.x = fmaf(xv.y, w1.x, acc.x); acc.y = fmaf(xv.y, w1.y, acc.y);
            acc.x = fmaf(xv.z, w2.x, acc.x); acc.y = fmaf(xv.z, w2.y, acc.y);
            acc.x = fmaf(xv.w, w3.x, acc.x); acc.y = fmaf(xv.w, w3.y, acc.y);
        }
        if (n0 + r < n) *(float2*)(g_h1p + (n0 + r) * HDIM + og) = acc;
    } else {
        const int p0 = __ldg(pos + 0), p1 = __ldg(pos + 1), p2 = __ldg(pos + 2),
                  p3 = __ldg(pos + 3), p4 = __ldg(pos + 4);
        if (idx == 0 && t < AA) { int p = __ldg(pos + t); if (p >= 0) mark2_push(p); }
        if ((E & 3) == 0) {
            int v = idx * 256 + t;
            if (v < (E >> 2)) {
                int4 d4 = __ldg((const int4*)dst + v);
                float4 w4 = __ldg((const float4*)ew + v);
                atomicAdd(&g_z.deg[d4.x], w4.x);
                atomicAdd(&g_z.deg[d4.y], w4.y);
                atomicAdd(&g_z.deg[d4.z], w4.z);
                atomicAdd(&g_z.deg[d4.w], w4.w);
                int dd[4] = {d4.x, d4.y, d4.z, d4.w};
#pragma unroll
                for (int j = 0; j < 4; j++) {
                    int d = dd[j];
                    if (d == p0 || d == p1 || d == p2 || d == p3 || d == p4) {
                        int e = v * 4 + j;
                        mark2_push(__ldg(src + e));
                        int k = atomicAdd(&g_z.cnt[1], 1);
                        if (k < L3CAP) g_list3[k] = e;
                    }
                }
            }
        } else {
#pragma unroll
            for (int j = 0; j < 4; j++) {
                int e = idx * 1024 + j * 256 + t;
                if (e < E) {
                    int d = __ldg(dst + e);
                    atomicAdd(&g_z.deg[d], __ldg(ew + e));
                    if (d == p0 || d == p1 || d == p2 || d == p3 || d == p4) {
                        mark2_push(__ldg(src + e));
                        int k = atomicAdd(&g_z.cnt[1], 1);
                        if (k < L3CAP) g_list3[k] = e;
                    }
                }
            }
        }
    }
}

// ======================= K2: rsqrt-prep (+nl2->nl1) ∥ scan2 =======================
__global__ void __launch_bounds__(TPB) k2_prep_scan2(
        const int* __restrict__ src, const int* __restrict__ dst,
        int n, int E, int P) {
    int b = blockIdx.x, t = threadIdx.x;
    if (b < P) {
        if ((n & 3) == 0) {
            int v = b * 256 + t;
            if (v < (n >> 2)) {
                float4 dv = *(float4*)(g_z.deg + v * 4);
                dv.x = rsqrtf(1.f + dv.x); dv.y = rsqrtf(1.f + dv.y);
                dv.z = rsqrtf(1.f + dv.z); dv.w = rsqrtf(1.f + dv.w);
                *(float4*)(g_z.deg + v * 4) = dv;
            }
        } else {
#pragma unroll
            for (int j = 0; j < 4; j++) {
                int i = b * 1024 + j * 256 + t;
                if (i < n) g_z.deg[i] = rsqrtf(1.f + g_z.deg[i]);
            }
        }
        if (b == 0) {
            int c3 = g_z.cnt[3]; if (c3 > NMAXC) c3 = NMAXC;
            for (int i = t; i < c3; i += 256) mark1_push(g_nl2[i]);
        }
    } else {
        int idx = b - P;
        if ((E & 3) == 0) {
            int v = idx * 256 + t;
            if (v < (E >> 2)) {
                int4 d4 = __ldg((const int4*)dst + v);
                int dd[4] = {d4.x, d4.y, d4.z, d4.w};
#pragma unroll
                for (int j = 0; j < 4; j++) {
                    int d = dd[j];
                    if ((g_z.n2bits[d >> 5] >> (d & 31)) & 1u) {
                        int e = v * 4 + j;
                        mark1_push(__ldg(src + e));
                        int k = atomicAdd(&g_z.cnt[0], 1);
                        if (k < L2CAP) g_list2[k] = e;
                    }
                }
            }
        } else {
#pragma unroll
            for (int j = 0; j < 4; j++) {
                int e = idx * 1024 + j * 256 + t;
                if (e < E) {
                    int d = __ldg(dst + e);
                    if ((g_z.n2bits[d >> 5] >> (d & 31)) & 1u) {
                        mark1_push(__ldg(src + e));
                        int k = atomicAdd(&g_z.cnt[0], 1);
                        if (k < L2CAP) g_list2[k] = e;
                    }
                }
            }
        }
    }
}

// ======================= K3: edge1 full scan, warp-cooperative gated scatter =======================
__global__ void __launch_bounds__(TPB) k3_edge1(
        const int* __restrict__ src, const int* __restrict__ dst,
        const float* __restrict__ ew, int E) {
    int b = blockIdx.x, t = threadIdx.x, lane = t & 31;
    if ((E & 3) == 0) {
        int v = b * 256 + t;
        bool inr = v < (E >> 2);
        int4 d4 = make_int4(0, 0, 0, 0);
        if (inr) d4 = __ldg((const int4*)dst + v);
        int dd[4] = {d4.x, d4.y, d4.z, d4.w};
#pragma unroll
        for (int j = 0; j < 4; j++) {
            int d = dd[j];
            bool hit = inr && ((g_z.n1bits[d >> 5] >> (d & 31)) & 1u);
            unsigned m = __ballot_sync(0xffffffffu, hit);
            while (m) {
                int l = __ffs(m) - 1;
                m &= m - 1;
                int vv = __shfl_sync(0xffffffffu, v, l);
                int ds = __shfl_sync(0xffffffffu, d, l);
                int e = vv * 4 + j;
                int ss = __ldg(src + e);
                float nrm = g_z.deg[ss] * __ldg(ew + e) * g_z.deg[ds];
                if (lane < HDIM)
                    atomicAdd(&g_agg1[ds * HDIM + lane], nrm * g_h1p[ss * HDIM + lane]);
            }
        }
    } else {
#pragma unroll
        for (int j = 0; j < 4; j++) {
            int e = b * 1024 + j * 256 + t;
            if (e < E) {
                int d = __ldg(dst + e);
                if ((g_z.n1bits[d >> 5] >> (d & 31)) & 1u) {
                    int s = __ldg(src + e);
                    float nrm = g_z.deg[s] * __ldg(ew + e) * g_z.deg[d];
#pragma unroll
                    for (int k = 0; k < HDIM; k++)
                        atomicAdd(&g_agg1[d * HDIM + k], nrm * g_h1p[s * HDIM + k]);
                }
            }
        }
    }
}

// ======================= K4: persistent tail =======================
__device__ __forceinline__ void gsync(int nblk, int idx) {
    __syncthreads();
    if (threadIdx.x == 0) {
        __threadfence();
        unsigned target = (unsigned)nblk * (unsigned)idx;
        atomicAdd(&g_z.arrive, 1u);
        while (*(volatile unsigned*)&g_z.arrive < target) __nanosleep(32);
        __threadfence();
    }
    __syncthreads();
}

__global__ void __launch_bounds__(TPB) k4_tail(
    const int* __restrict__ src, const int* __restrict__ dst,
    const float* __restrict__ ew, const int* __restrict__ pos,
    const float* __restrict__ b1, const float* __restrict__ W2,
    const float* __restrict__ b2,
    const float* __restrict__ W3, const float* __restrict__ b3,
    const float* __restrict__ fcW1, const float* __restrict__ fcb1,
    const float* __restrict__ fcW2, const float* __restrict__ fcb2,
    const float* __restrict__ fcW3, const float* __restrict__ fcb3,
    float* __restrict__ out)
{
    __shared__ float shw[HDIM * HDIM];
    __shared__ float shb[HDIM];
    int t = threadIdx.x, b = blockIdx.x, nblk = gridDim.x;
    int gtid = b * TPB + t, gstr = nblk * TPB;
    int lane = t & 31, warp = t >> 5;

    // --- phase A: node1 on blocks 0..31  |  L2-warm MLP weights on blocks 32..63 ---
    if (b < 32) {
        shw[t] = __ldg(W2 + t);
        if (t < HDIM) shb[t] = __ldg(b1 + t);
        __syncthreads();
        int c1 = g_z.cnt[2]; if (c1 > NMAXC) c1 = NMAXC;
        for (int i = b * TPB + t; i < c1; i += 32 * TPB) {
            int nd = g_nl1[i];
            float di = g_z.deg[nd], d2 = di * di;
            float h[HDIM];
            const float4* ar = (const float4*)(g_agg1 + nd * HDIM);
            const float4* hr = (const float4*)(g_h1p + nd * HDIM);
#pragma unroll
            for (int v4 = 0; v4 < 4; v4++) {
                float4 a = ar[v4], p = hr[v4];
                h[v4*4+0] = fmaxf(a.x + d2 * p.x + shb[v4*4+0], 0.f);
                h[v4*4+1] = fmaxf(a.y + d2 * p.y + shb[v4*4+1], 0.f);
                h[v4*4+2] = fmaxf(a.z + d2 * p.z + shb[v4*4+2], 0.f);
                h[v4*4+3] = fmaxf(a.w + d2 * p.w + shb[v4*4+3], 0.f);
            }
            float* op = g_h2p + nd * HDIM;
#pragma unroll
            for (int og = 0; og < HDIM; og += 4) {
                float4 acc = make_float4(0.f, 0.f, 0.f, 0.f);
#pragma unroll
                for (int k = 0; k < HDIM; k++) {
                    const float* wr = shw + k * HDIM + og;
                    acc.x = fmaf(h[k], wr[0], acc.x);
                    acc.y = fmaf(h[k], wr[1], acc.y);
                    acc.z = fmaf(h[k], wr[2], acc.z);
                    acc.w = fmaf(h[k], wr[3], acc.w);
                }
                *(float4*)(op + og) = acc;
            }
        }
    } else {
        // warm L2 with head weights (runs concurrent with node1)
        int wt = (b - 32) * TPB + t, ws = 32 * TPB;
        float s = 0.f;
        const float4* f1 = (const float4*)fcW1;   // 16000 float4
        for (int i = wt; i < (AA * EMB * HID) / 4; i += ws) { float4 v = __ldg(f1 + i); s += v.x + v.y + v.z + v.w; }
        const float4* f2 = (const float4*)fcW2;   // 4096 float4
        for (int i = wt; i < (HID * HID) / 4; i += ws)      { float4 v = __ldg(f2 + i); s += v.x + v.y + v.z + v.w; }
        const float4* f3 = (const float4*)W3;     // 400 float4
        for (int i = wt; i < (HDIM * EMB) / 4; i += ws)     { float4 v = __ldg(f3 + i); s += v.x + v.y + v.z + v.w; }
        for (int i = wt; i < HID * AA; i += ws)             { s += __ldg(fcW3 + i); }
        if (s == 123456789.0f) g_dummy = s;       // never true; defeats DCE
    }
    gsync(nblk, 1);

    // --- edge2 ---
    {
        int c2 = g_z.cnt[0]; if (c2 > L2CAP) c2 = L2CAP;
        int total = c2 * HDIM;
        for (int i = gtid; i < total; i += gstr) {
            int e = g_list2[i >> 4], k = i & 15;
            int s = __ldg(src + e), d = __ldg(dst + e);
            float nrm = g_z.deg[s] * __ldg(ew + e) * g_z.deg[d];
            atomicAdd(&g_agg2[d * HDIM + k], nrm * g_h2p[s * HDIM + k]);
        }
    }
    gsync(nblk, 2);

    // --- node2 ---
    {
        int c3 = g_z.cnt[3]; if (c3 > NMAXC) c3 = NMAXC;
        for (int i = gtid; i < c3; i += gstr) {
            int nd = g_nl2[i];
            float di = g_z.deg[nd], d2 = di * di;
            const float4* ar = (const float4*)(g_agg2 + nd * HDIM);
            const float4* pr = (const float4*)(g_h2p + nd * HDIM);
            float4* op = (float4*)(g_h2 + nd * HDIM);
#pragma unroll
            for (int v4 = 0; v4 < 4; v4++) {
                float4 a = ar[v4], p = pr[v4];
                float4 o;
                o.x = fmaxf(a.x + d2 * p.x + __ldg(b2 + v4*4+0), 0.f);
                o.y = fmaxf(a.y + d2 * p.y + __ldg(b2 + v4*4+1), 0.f);
                o.z = fmaxf(a.z + d2 * p.z + __ldg(b2 + v4*4+2), 0.f);
                o.w = fmaxf(a.w + d2 * p.w + __ldg(b2 + v4*4+3), 0.f);
                op[v4] = o;
            }
        }
    }
    gsync(nblk, 3);

    // --- edge3 ---
    {
        const int p0 = __ldg(pos+0), p1 = __ldg(pos+1), p2 = __ldg(pos+2),
                  p3 = __ldg(pos+3), p4 = __ldg(pos+4);
        int parr[AA] = {p0, p1, p2, p3, p4};
        int c3e = g_z.cnt[1]; if (c3e > L3CAP) c3e = L3CAP;
        int total = c3e * HDIM;
        for (int i = gtid; i < total; i += gstr) {
            int e = g_list3[i >> 4], k = i & 15;
            int s = __ldg(src + e), d = __ldg(dst + e);
            float nrm = g_z.deg[s] * __ldg(ew + e) * g_z.deg[d];
            float val = nrm * g_h2[s * HDIM + k];
#pragma unroll
            for (int a = 0; a < AA; a++)
                if (d == parr[a]) atomicAdd(&g_z.agg3[a * HDIM + k], val);
        }
    }
    gsync(nblk, 4);

    // --- head (block 0 only, warp-parallel MLP) ---
    if (b == 0) {
        __shared__ float shv[AA * HDIM];
        __shared__ float shz[AA * EMB];
        __shared__ float part[8][HID];
        __shared__ float sho1[HID];
        __shared__ float sho2[HID];

        if (t < AA * HDIM) {
            int a = t >> 4, k = t & 15;
            int p = __ldg(pos + a);
            float val = 0.f;
            if (p >= 0) {
                float di = g_z.deg[p];
                val = g_z.agg3[t] + di * di * g_h2[p * HDIM + k];
            }
            shv[t] = val;
        }
        __syncthreads();
        for (int j = t; j < AA * EMB; j += TPB) {
            int a = j / EMB, c = j % EMB;
            int p = __ldg(pos + a);
            float acc;
            if (p < 0) acc = -1.f;
            else {
                acc = __ldg(b3 + c);
#pragma unroll
                for (int k = 0; k < HDIM; k++)
                    acc = fmaf(shv[a * HDIM + k], __ldg(W3 + k * EMB + c), acc);
            }
            shz[j] = acc;
        }
        __syncthreads();

        // o1: warp w handles j in [w*63, min(500,(w+1)*63)); lanes cover 128 outputs (4 each)
        {
            int j0 = warp * 63;
            int j1 = j0 + 63; if (warp == 7) j1 = AA * EMB;   // 7*63=441..500
            float a0 = 0.f, a1 = 0.f, a2 = 0.f, a3 = 0.f;
            for (int j = j0; j < j1; j++) {
                float zj = shz[j];
                const float* row = fcW1 + j * HID;
                a0 = fmaf(zj, __ldg(row + lane      ), a0);
                a1 = fmaf(zj, __ldg(row + lane + 32 ), a1);
                a2 = fmaf(zj, __ldg(row + lane + 64 ), a2);
                a3 = fmaf(zj, __ldg(row + lane + 96 ), a3);
            }
            part[warp][lane      ] = a0;
            part[warp][lane + 32 ] = a1;
            part[warp][lane + 64 ] = a2;
            part[warp][lane + 96 ] = a3;
        }
        __syncthreads();
        if (t < HID) {
            float acc = __ldg(fcb1 + t);
#pragma unroll
            for (int w = 0; w < 8; w++) acc += part[w][t];
            sho1[t] = fmaxf(acc, 0.f);
        }
        __syncthreads();

        // o2: warp w handles j in [w*16, (w+1)*16)
        {
            int j0 = warp * 16, j1 = j0 + 16;
            float a0 = 0.f, a1 = 0.f, a2 = 0.f, a3 = 0.f;
            for (int j = j0; j < j1; j++) {
                float oj = sho1[j];
                const float* row = fcW2 + j * HID;
                a0 = fmaf(oj, __ldg(row + lane      ), a0);
                a1 = fmaf(oj, __ldg(row + lane + 32 ), a1);
                a2 = fmaf(oj, __ldg(row + lane + 64 ), a2);
                a3 = fmaf(oj, __ldg(row + lane + 96 ), a3);
            }
            part[warp][lane      ] = a0;
            part[warp][lane + 32 ] = a1;
            part[warp][lane + 64 ] = a2;
            part[warp][lane + 96 ] = a3;
        }
        __syncthreads();
        if (t < HID) {
            float acc = __ldg(fcb2 + t);
#pragma unroll
            for (int w = 0; w < 8; w++) acc += part[w][t];
            sho2[t] = fmaxf(acc, 0.f);
        }
        __syncthreads();

        // out: warps 0..4, lane-strided over 128, shfl reduce
        if (warp < AA) {
            float acc = 0.f;
#pragma unroll
            for (int k = 0; k < HID; k += 32)
                acc = fmaf(sho2[k + lane], __ldg(fcW3 + (k + lane) * AA + warp), acc);
#pragma unroll
            for (int off = 16; off > 0; off >>= 1)
                acc += __shfl_down_sync(0xffffffffu, acc, off);
            if (lane == 0) out[warp] = acc + __ldg(fcb3 + warp);
        }
    }
}

extern "C" void kernel_launch(void* const* d_in, const int* in_sizes, int n_in,
                              void* d_out, int out_size) {
    const float* x    = (const float*)d_in[0];
    const int*   ei   = (const int*)  d_in[1];
    const float* ew   = (const float*)d_in[2];
    const int*   pos  = (const int*)  d_in[3];
    const float* W1   = (const float*)d_in[4];
    const float* b1   = (const float*)d_in[5];
    const float* W2   = (const float*)d_in[6];
    const float* b2   = (const float*)d_in[7];
    const float* W3   = (const float*)d_in[8];
    const float* b3   = (const float*)d_in[9];
    const float* fcW1 = (const float*)d_in[10];
    const float* fcb1 = (const float*)d_in[11];
    const float* fcW2 = (const float*)d_in[12];
    const float* fcb2 = (const float*)d_in[13];
    const float* fcW3 = (const float*)d_in[14];
    const float* fcb3 = (const float*)d_in[15];

    int N = in_sizes[0] / F_IN;
    int E = in_sizes[1] / 2;
    const int* src = ei;
    const int* dst = ei + E;
    float* out = (float*)d_out;

    void* zp;
    cudaGetSymbolAddress(&zp, g_z);
    cudaMemsetAsync(zp, 0, sizeof(ZeroBlob));

    int T = (N + GN - 1) / GN;
    int S = (E + 1023) / 1024;
    int P = (N + 1023) / 1024;

    k1_gemm_scanA<<<T + S, TPB>>>(x, W1, src, dst, ew, pos, N, E, T, S);
    k2_prep_scan2<<<P + S, TPB>>>(src, dst, N, E, P);
    k3_edge1     <<<S, TPB>>>(src, dst, ew, E);
    k4_tail      <<<64, TPB>>>(src, dst, ew, pos, b1, W2, b2, W3, b3,
                               fcW1, fcb1, fcW2, fcb2, fcW3, fcb3, out);
}